// round 5
// baseline (speedup 1.0000x reference)
#include <cuda_runtime.h>
#include <cuda_bf16.h>
#include <cstdint>
#include <cstddef>

#define DEVINL __device__ __forceinline__

// Problem dims
static constexpr int M = 8192;   // 4*2048 rows of activations
static constexpr int N = 4096;   // output features
static constexpr int K = 4096;   // contraction dim

// GEMM tiling (legacy mma.sync int8 path: sm_103 base target, no 'a' features)
static constexpr int BM = 128;
static constexpr int BN = 128;
static constexpr int BK = 64;
static constexpr int STAGES = 4;
static constexpr int NKCH = K / BK;        // 64

static constexpr int ROWB = 80;            // 64B row + 16B pad (conflict-free LDS)
static constexpr int A_STAGE = BM * ROWB;  // 10240
static constexpr int STAGE_BYTES = 2 * A_STAGE;            // A+B = 20480
static constexpr int SMEM_TOTAL = STAGES * STAGE_BYTES;    // 81920

// ---------------- scratch (device globals: allocation-free rule) -------------
__device__ int8_t g_Xq[(size_t)M * K];     // 32 MB quantized activations [M][K]
__device__ int8_t g_Kq[(size_t)N * K];     // 16 MB quantized weights     [F][D]
__device__ float  g_sx[M];
__device__ float  g_sk[N];
__device__ float  g_pk[32 * N];            // partial column amax

// ---------------- PTX helpers ----------------
DEVINL void cp16(uint32_t s, const void* g) {
    asm volatile("cp.async.cg.shared.global [%0], [%1], 16;" :: "r"(s), "l"(g));
}
DEVINL void cp_commit() { asm volatile("cp.async.commit_group;" ::: "memory"); }
template <int Nw> DEVINL void cp_wait() {
    asm volatile("cp.async.wait_group %0;" :: "n"(Nw) : "memory");
}
DEVINL uint32_t smem_u32(const void* p) {
    uint32_t a;
    asm("{ .reg .u64 t; cvta.to.shared.u64 t, %1; cvt.u32.u64 %0, t; }" : "=r"(a) : "l"(p));
    return a;
}
DEVINL void mma8(int* c, const uint32_t* a, const uint32_t* b) {
    asm volatile(
        "mma.sync.aligned.m16n8k32.row.col.s32.s8.s8.s32 "
        "{%0,%1,%2,%3}, {%4,%5,%6,%7}, {%8,%9}, {%0,%1,%2,%3};"
        : "+r"(c[0]), "+r"(c[1]), "+r"(c[2]), "+r"(c[3])
        : "r"(a[0]), "r"(a[1]), "r"(a[2]), "r"(a[3]), "r"(b[0]), "r"(b[1]));
}

DEVINL int quant1(float v, float scale) {
    float q = rintf(__fdiv_rn(v, scale));
    q = fminf(fmaxf(q, -127.0f), 127.0f);
    return __float2int_rn(q);
}
DEVINL uint32_t pack4(int q0, int q1, int q2, int q3) {
    return (uint32_t)(q0 & 0xFF) | ((uint32_t)(q1 & 0xFF) << 8) |
           ((uint32_t)(q2 & 0xFF) << 16) | ((uint32_t)(q3 & 0xFF) << 24);
}

// ---------------- kernel 1: per-row quant of activations ----------------
__global__ void __launch_bounds__(256) quantX_kernel(const float* __restrict__ x) {
    int row = blockIdx.x;
    const float4* xr = reinterpret_cast<const float4*>(x + (size_t)row * K);
    float4 v[4];
    float am = 0.0f;
#pragma unroll
    for (int i = 0; i < 4; i++) {
        v[i] = xr[threadIdx.x + i * 256];
        am = fmaxf(am, fmaxf(fmaxf(fabsf(v[i].x), fabsf(v[i].y)),
                             fmaxf(fabsf(v[i].z), fabsf(v[i].w))));
    }
#pragma unroll
    for (int off = 16; off > 0; off >>= 1)
        am = fmaxf(am, __shfl_xor_sync(0xFFFFFFFFu, am, off));
    __shared__ float s_w[8];
    __shared__ float s_scale;
    if ((threadIdx.x & 31) == 0) s_w[threadIdx.x >> 5] = am;
    __syncthreads();
    if (threadIdx.x == 0) {
        float m = s_w[0];
#pragma unroll
        for (int i = 1; i < 8; i++) m = fmaxf(m, s_w[i]);
        float sc = fmaxf(m, 1e-6f) / 127.0f;
        s_scale = sc;
        g_sx[row] = sc;
    }
    __syncthreads();
    float sc = s_scale;
    uint32_t* xo = reinterpret_cast<uint32_t*>(&g_Xq[(size_t)row * K]);
#pragma unroll
    for (int i = 0; i < 4; i++) {
        xo[threadIdx.x + i * 256] =
            pack4(quant1(v[i].x, sc), quant1(v[i].y, sc),
                  quant1(v[i].z, sc), quant1(v[i].w, sc));
    }
}

// ---------------- kernel 2: partial column amax of weights ----------------
__global__ void __launch_bounds__(256) colAmax_kernel(const float* __restrict__ w) {
    int f = blockIdx.x * 256 + threadIdx.x;
    int d0 = blockIdx.y * 128;
    float am = 0.0f;
#pragma unroll 4
    for (int d = 0; d < 128; d++)
        am = fmaxf(am, fabsf(w[(size_t)(d0 + d) * N + f]));
    g_pk[blockIdx.y * N + f] = am;
}

// ---------------- kernel 3: reduce column amax -> scales ----------------
__global__ void __launch_bounds__(256) colReduce_kernel() {
    int f = blockIdx.x * 256 + threadIdx.x;
    float am = 0.0f;
#pragma unroll
    for (int r = 0; r < 32; r++) am = fmaxf(am, g_pk[r * N + f]);
    g_sk[f] = fmaxf(am, 1e-6f) / 127.0f;
}

// ---------------- kernel 4: quant + transpose weights -> g_Kq[F][D] ----------------
__global__ void __launch_bounds__(256) transQuant_kernel(const float* __restrict__ w) {
    __shared__ int8_t tile[32][33];
    __shared__ float sks[32];
    int tx = threadIdx.x, ty = threadIdx.y;
    int f0 = blockIdx.x * 32, d0 = blockIdx.y * 32;
    if (ty == 0) sks[tx] = g_sk[f0 + tx];
    __syncthreads();
#pragma unroll
    for (int r = 0; r < 4; r++) {
        int d = d0 + ty + r * 8;
        float v = w[(size_t)d * N + f0 + tx];
        tile[ty + r * 8][tx] = (int8_t)quant1(v, sks[tx]);
    }
    __syncthreads();
#pragma unroll
    for (int r = 0; r < 4; r++) {
        int f = f0 + ty + r * 8;
        g_Kq[(size_t)f * K + d0 + tx] = tile[tx][ty + r * 8];
    }
}

// ---------------- kernel 5: int8 mma.sync GEMM + scaling epilogue ----------------
DEVINL void load_chunk(uint32_t sbase, char* smem, int stage, int ck, int mbase, int nbase) {
    uint32_t sA = sbase + stage * STAGE_BYTES;
    uint32_t sB = sA + A_STAGE;
    int t = threadIdx.x;
    int k0 = ck * BK;
    const int8_t* xr = &g_Xq[(size_t)mbase * K + k0];
    const int8_t* kr = &g_Kq[(size_t)nbase * K + k0];
#pragma unroll
    for (int n = 0; n < 4; n++) {
        int s = t + n * 128;          // 0..511 A segments (128 rows x 4 x 16B)
        int r = s >> 2, seg = s & 3;
        cp16(sA + (uint32_t)(r * ROWB + seg * 16), xr + (size_t)r * K + seg * 16);
    }
#pragma unroll
    for (int n = 0; n < 4; n++) {
        int s = t + n * 128;          // B segments
        int r = s >> 2, seg = s & 3;
        cp16(sB + (uint32_t)(r * ROWB + seg * 16), kr + (size_t)r * K + seg * 16);
    }
}

__global__ void __launch_bounds__(128) gemm_kernel(float* __restrict__ out) {
    extern __shared__ char smem[];
    uint32_t sbase = smem_u32(smem);
    int tid = threadIdx.x;
    int wid = tid >> 5, lane = tid & 31;
    int grp = lane >> 2, qid = lane & 3;
    int mwarp = (wid >> 1) * 64;      // warp grid 2(M) x 2(N), warp tile 64x64
    int nwarp = (wid & 1) * 64;
    int mbase = blockIdx.y * BM;
    int nbase = blockIdx.x * BN;

    int acc[4][8][4];                 // [mtile m16][ntile n8][frag]
#pragma unroll
    for (int mt = 0; mt < 4; mt++)
#pragma unroll
        for (int nt = 0; nt < 8; nt++)
#pragma unroll
            for (int r = 0; r < 4; r++) acc[mt][nt][r] = 0;

    // prologue: stages 0..2
    load_chunk(sbase, smem, 0, 0, mbase, nbase); cp_commit();
    load_chunk(sbase, smem, 1, 1, mbase, nbase); cp_commit();
    load_chunk(sbase, smem, 2, 2, mbase, nbase); cp_commit();

    for (int i = 0; i < NKCH; i++) {
        cp_wait<2>();
        __syncthreads();

        const char* cA = smem + (i % STAGES) * STAGE_BYTES;
        const char* cB = cA + A_STAGE;
#pragma unroll
        for (int ks = 0; ks < 2; ks++) {
            uint32_t a[4][4], b[8][2];
#pragma unroll
            for (int mt = 0; mt < 4; mt++) {
                const char* p = cA + (mwarp + mt * 16 + grp) * ROWB + ks * 32 + qid * 4;
                a[mt][0] = *reinterpret_cast<const uint32_t*>(p);
                a[mt][1] = *reinterpret_cast<const uint32_t*>(p + 8 * ROWB);
                a[mt][2] = *reinterpret_cast<const uint32_t*>(p + 16);
                a[mt][3] = *reinterpret_cast<const uint32_t*>(p + 8 * ROWB + 16);
            }
#pragma unroll
            for (int nt = 0; nt < 8; nt++) {
                const char* p = cB + (nwarp + nt * 8 + grp) * ROWB + ks * 32 + qid * 4;
                b[nt][0] = *reinterpret_cast<const uint32_t*>(p);
                b[nt][1] = *reinterpret_cast<const uint32_t*>(p + 16);
            }
#pragma unroll
            for (int mt = 0; mt < 4; mt++)
#pragma unroll
                for (int nt = 0; nt < 8; nt++)
                    mma8(acc[mt][nt], a[mt], b[nt]);
        }

        int j = i + 3;
        if (j < NKCH) load_chunk(sbase, smem, j % STAGES, j, mbase, nbase);
        cp_commit();   // always commit to keep wait_group accounting aligned
    }

    // epilogue: dequant by sx[row] * sk[col], store fp32
#pragma unroll
    for (int mt = 0; mt < 4; mt++) {
        int r0 = mbase + mwarp + mt * 16 + grp;
        int r1 = r0 + 8;
        float sx0 = g_sx[r0], sx1 = g_sx[r1];
        float* o0 = out + (size_t)r0 * N;
        float* o1 = out + (size_t)r1 * N;
#pragma unroll
        for (int nt = 0; nt < 8; nt++) {
            int c0 = nbase + nwarp + nt * 8 + qid * 2;
            float k0 = g_sk[c0], k1 = g_sk[c0 + 1];
            float2 v0, v1;
            v0.x = (float)acc[mt][nt][0] * sx0 * k0;
            v0.y = (float)acc[mt][nt][1] * sx0 * k1;
            v1.x = (float)acc[mt][nt][2] * sx1 * k0;
            v1.y = (float)acc[mt][nt][3] * sx1 * k1;
            *reinterpret_cast<float2*>(o0 + c0) = v0;
            *reinterpret_cast<float2*>(o1 + c0) = v1;
        }
    }
}

// ---------------- launcher ----------------
extern "C" void kernel_launch(void* const* d_in, const int* in_sizes, int n_in,
                              void* d_out, int out_size) {
    const float* x = (const float*)d_in[0];   // [4,2048,4096]
    const float* w = (const float*)d_in[1];   // [4096,4096]
    float* out = (float*)d_out;               // [4,2048,4096]

    cudaFuncSetAttribute(gemm_kernel, cudaFuncAttributeMaxDynamicSharedMemorySize, SMEM_TOTAL);

    quantX_kernel<<<M, 256>>>(x);
    colAmax_kernel<<<dim3(N / 256, 32), 256>>>(w);
    colReduce_kernel<<<N / 256, 256>>>();
    transQuant_kernel<<<dim3(N / 32, K / 32), dim3(32, 8)>>>(w);
    gemm_kernel<<<dim3(N / BN, M / BM), 128, SMEM_TOTAL>>>(out);
}

// round 6
// speedup vs baseline: 1.0255x; 1.0255x over previous
#include <cuda_runtime.h>
#include <cuda_bf16.h>
#include <cstdint>
#include <cstddef>

#define DEVINL __device__ __forceinline__

// Problem dims
static constexpr int M = 8192;   // 4*2048 rows of activations
static constexpr int N = 4096;   // output features
static constexpr int K = 4096;   // contraction dim

// GEMM tiling (legacy mma.sync int8 path: sm_103 base PTX target, no 'a' features)
static constexpr int BM = 128;
static constexpr int BN = 128;
static constexpr int BK = 64;
static constexpr int STAGES = 4;
static constexpr int NKCH = K / BK;        // 64

static constexpr int ROWB = 80;            // 64B row + 16B pad (conflict-free LDS)
static constexpr int A_STAGE = BM * ROWB;  // 10240
static constexpr int STAGE_BYTES = 2 * A_STAGE;            // A+B = 20480
static constexpr int SMEM_TOTAL = STAGES * STAGE_BYTES;    // 81920

// ---------------- scratch (device globals: allocation-free rule) -------------
__device__ int8_t g_Xq[(size_t)M * K];     // 32 MB quantized activations [M][K]
__device__ int8_t g_Kq[(size_t)N * K];     // 16 MB quantized weights     [F][D]
__device__ float  g_sx[M];
__device__ float  g_sk[N];
__device__ float  g_pk[32 * N];            // partial column amax

// ---------------- PTX helpers ----------------
DEVINL void cp16(uint32_t s, const void* g) {
    asm volatile("cp.async.cg.shared.global [%0], [%1], 16;" :: "r"(s), "l"(g));
}
DEVINL void cp_commit() { asm volatile("cp.async.commit_group;" ::: "memory"); }
template <int Nw> DEVINL void cp_wait() {
    asm volatile("cp.async.wait_group %0;" :: "n"(Nw) : "memory");
}
DEVINL uint32_t smem_u32(const void* p) {
    uint32_t a;
    asm("{ .reg .u64 t; cvta.to.shared.u64 t, %1; cvt.u32.u64 %0, t; }" : "=r"(a) : "l"(p));
    return a;
}
DEVINL void mma8(int* c, const uint32_t* a, const uint32_t* b) {
    asm volatile(
        "mma.sync.aligned.m16n8k32.row.col.s32.s8.s8.s32 "
        "{%0,%1,%2,%3}, {%4,%5,%6,%7}, {%8,%9}, {%0,%1,%2,%3};"
        : "+r"(c[0]), "+r"(c[1]), "+r"(c[2]), "+r"(c[3])
        : "r"(a[0]), "r"(a[1]), "r"(a[2]), "r"(a[3]), "r"(b[0]), "r"(b[1]));
}

DEVINL int quant1(float v, float scale) {
    float q = rintf(__fdiv_rn(v, scale));
    q = fminf(fmaxf(q, -127.0f), 127.0f);
    return __float2int_rn(q);
}
DEVINL uint32_t pack4(int q0, int q1, int q2, int q3) {
    return (uint32_t)(q0 & 0xFF) | ((uint32_t)(q1 & 0xFF) << 8) |
           ((uint32_t)(q2 & 0xFF) << 16) | ((uint32_t)(q3 & 0xFF) << 24);
}

// ---------------- kernel 1: per-row quant of activations ----------------
__global__ void __launch_bounds__(256) quantX_kernel(const float* __restrict__ x) {
    int row = blockIdx.x;
    const float4* xr = reinterpret_cast<const float4*>(x + (size_t)row * K);
    float4 v[4];
    float am = 0.0f;
#pragma unroll
    for (int i = 0; i < 4; i++) {
        v[i] = xr[threadIdx.x + i * 256];
        am = fmaxf(am, fmaxf(fmaxf(fabsf(v[i].x), fabsf(v[i].y)),
                             fmaxf(fabsf(v[i].z), fabsf(v[i].w))));
    }
#pragma unroll
    for (int off = 16; off > 0; off >>= 1)
        am = fmaxf(am, __shfl_xor_sync(0xFFFFFFFFu, am, off));
    __shared__ float s_w[8];
    __shared__ float s_scale;
    if ((threadIdx.x & 31) == 0) s_w[threadIdx.x >> 5] = am;
    __syncthreads();
    if (threadIdx.x == 0) {
        float m = s_w[0];
#pragma unroll
        for (int i = 1; i < 8; i++) m = fmaxf(m, s_w[i]);
        float sc = fmaxf(m, 1e-6f) / 127.0f;
        s_scale = sc;
        g_sx[row] = sc;
    }
    __syncthreads();
    float sc = s_scale;
    uint32_t* xo = reinterpret_cast<uint32_t*>(&g_Xq[(size_t)row * K]);
#pragma unroll
    for (int i = 0; i < 4; i++) {
        xo[threadIdx.x + i * 256] =
            pack4(quant1(v[i].x, sc), quant1(v[i].y, sc),
                  quant1(v[i].z, sc), quant1(v[i].w, sc));
    }
}

// ---------------- kernel 2: partial column amax of weights ----------------
__global__ void __launch_bounds__(256) colAmax_kernel(const float* __restrict__ w) {
    int f = blockIdx.x * 256 + threadIdx.x;
    int d0 = blockIdx.y * 128;
    float am = 0.0f;
#pragma unroll 4
    for (int d = 0; d < 128; d++)
        am = fmaxf(am, fabsf(w[(size_t)(d0 + d) * N + f]));
    g_pk[blockIdx.y * N + f] = am;
}

// ---------------- kernel 3: reduce column amax -> scales ----------------
__global__ void __launch_bounds__(256) colReduce_kernel() {
    int f = blockIdx.x * 256 + threadIdx.x;
    float am = 0.0f;
#pragma unroll
    for (int r = 0; r < 32; r++) am = fmaxf(am, g_pk[r * N + f]);
    g_sk[f] = fmaxf(am, 1e-6f) / 127.0f;
}

// ---------------- kernel 4: quant + transpose weights -> g_Kq[F][D] ----------------
__global__ void __launch_bounds__(256) transQuant_kernel(const float* __restrict__ w) {
    __shared__ int8_t tile[32][33];
    __shared__ float sks[32];
    int tx = threadIdx.x, ty = threadIdx.y;
    int f0 = blockIdx.x * 32, d0 = blockIdx.y * 32;
    if (ty == 0) sks[tx] = g_sk[f0 + tx];
    __syncthreads();
#pragma unroll
    for (int r = 0; r < 4; r++) {
        int d = d0 + ty + r * 8;
        float v = w[(size_t)d * N + f0 + tx];
        tile[ty + r * 8][tx] = (int8_t)quant1(v, sks[tx]);
    }
    __syncthreads();
#pragma unroll
    for (int r = 0; r < 4; r++) {
        int f = f0 + ty + r * 8;
        g_Kq[(size_t)f * K + d0 + tx] = tile[tx][ty + r * 8];
    }
}

// ---------------- profiling alignment: launch idx 4 (so gemm lands on idx 5) --
__global__ void noop_kernel() {}

// ---------------- kernel 5: int8 mma.sync GEMM + scaling epilogue ----------------
// 256 threads, 8 warps: warp grid 2(M) x 4(N), warp tile 64x32.
DEVINL void load_chunk(uint32_t sbase, int stage, int ck, int mbase, int nbase) {
    uint32_t sA = sbase + stage * STAGE_BYTES;
    uint32_t sB = sA + A_STAGE;
    int t = threadIdx.x;
    int k0 = ck * BK;
    const int8_t* xr = &g_Xq[(size_t)mbase * K + k0];
    const int8_t* kr = &g_Kq[(size_t)nbase * K + k0];
#pragma unroll
    for (int n = 0; n < 2; n++) {
        int s = t + n * 256;          // 0..511 A segments (128 rows x 4 x 16B)
        int r = s >> 2, seg = s & 3;
        cp16(sA + (uint32_t)(r * ROWB + seg * 16), xr + (size_t)r * K + seg * 16);
    }
#pragma unroll
    for (int n = 0; n < 2; n++) {
        int s = t + n * 256;          // B segments
        int r = s >> 2, seg = s & 3;
        cp16(sB + (uint32_t)(r * ROWB + seg * 16), kr + (size_t)r * K + seg * 16);
    }
}

__global__ void __launch_bounds__(256) gemm_kernel(float* __restrict__ out) {
    extern __shared__ char smem[];
    uint32_t sbase = smem_u32(smem);
    int tid = threadIdx.x;
    int wid = tid >> 5, lane = tid & 31;
    int grp = lane >> 2, qid = lane & 3;
    int mwarp = (wid >> 2) * 64;      // warp grid 2(M) x 4(N), warp tile 64x32
    int nwarp = (wid & 3) * 32;
    int mbase = blockIdx.y * BM;
    int nbase = blockIdx.x * BN;

    int acc[4][4][4];                 // [mtile m16][ntile n8][frag]
#pragma unroll
    for (int mt = 0; mt < 4; mt++)
#pragma unroll
        for (int nt = 0; nt < 4; nt++)
#pragma unroll
            for (int r = 0; r < 4; r++) acc[mt][nt][r] = 0;

    // prologue: stages 0..2
    load_chunk(sbase, 0, 0, mbase, nbase); cp_commit();
    load_chunk(sbase, 1, 1, mbase, nbase); cp_commit();
    load_chunk(sbase, 2, 2, mbase, nbase); cp_commit();

    for (int i = 0; i < NKCH; i++) {
        cp_wait<2>();
        __syncthreads();

        const char* cA = smem + (i % STAGES) * STAGE_BYTES;
        const char* cB = cA + A_STAGE;
#pragma unroll
        for (int ks = 0; ks < 2; ks++) {
            uint32_t a[4][4], b[4][2];
#pragma unroll
            for (int mt = 0; mt < 4; mt++) {
                const char* p = cA + (mwarp + mt * 16 + grp) * ROWB + ks * 32 + qid * 4;
                a[mt][0] = *reinterpret_cast<const uint32_t*>(p);
                a[mt][1] = *reinterpret_cast<const uint32_t*>(p + 8 * ROWB);
                a[mt][2] = *reinterpret_cast<const uint32_t*>(p + 16);
                a[mt][3] = *reinterpret_cast<const uint32_t*>(p + 8 * ROWB + 16);
            }
#pragma unroll
            for (int nt = 0; nt < 4; nt++) {
                const char* p = cB + (nwarp + nt * 8 + grp) * ROWB + ks * 32 + qid * 4;
                b[nt][0] = *reinterpret_cast<const uint32_t*>(p);
                b[nt][1] = *reinterpret_cast<const uint32_t*>(p + 16);
            }
#pragma unroll
            for (int mt = 0; mt < 4; mt++)
#pragma unroll
                for (int nt = 0; nt < 4; nt++)
                    mma8(acc[mt][nt], a[mt], b[nt]);
        }

        int j = i + 3;
        if (j < NKCH) load_chunk(sbase, j % STAGES, j, mbase, nbase);
        cp_commit();   // always commit to keep wait_group accounting aligned
    }

    // epilogue: dequant by sx[row] * sk[col], store fp32
#pragma unroll
    for (int mt = 0; mt < 4; mt++) {
        int r0 = mbase + mwarp + mt * 16 + grp;
        int r1 = r0 + 8;
        float sx0 = g_sx[r0], sx1 = g_sx[r1];
        float* o0 = out + (size_t)r0 * N;
        float* o1 = out + (size_t)r1 * N;
#pragma unroll
        for (int nt = 0; nt < 4; nt++) {
            int c0 = nbase + nwarp + nt * 8 + qid * 2;
            float k0 = g_sk[c0], k1 = g_sk[c0 + 1];
            float2 v0, v1;
            v0.x = (float)acc[mt][nt][0] * sx0 * k0;
            v0.y = (float)acc[mt][nt][1] * sx0 * k1;
            v1.x = (float)acc[mt][nt][2] * sx1 * k0;
            v1.y = (float)acc[mt][nt][3] * sx1 * k1;
            *reinterpret_cast<float2*>(o0 + c0) = v0;
            *reinterpret_cast<float2*>(o1 + c0) = v1;
        }
    }
}

// ---------------- launcher ----------------
extern "C" void kernel_launch(void* const* d_in, const int* in_sizes, int n_in,
                              void* d_out, int out_size) {
    const float* x = (const float*)d_in[0];   // [4,2048,4096]
    const float* w = (const float*)d_in[1];   // [4096,4096]
    float* out = (float*)d_out;               // [4,2048,4096]

    cudaFuncSetAttribute(gemm_kernel, cudaFuncAttributeMaxDynamicSharedMemorySize, SMEM_TOTAL);

    quantX_kernel<<<M, 256>>>(x);                                    // launch 0
    colAmax_kernel<<<dim3(N / 256, 32), 256>>>(w);                   // launch 1
    colReduce_kernel<<<N / 256, 256>>>();                            // launch 2
    transQuant_kernel<<<dim3(N / 32, K / 32), dim3(32, 8)>>>(w);     // launch 3
    noop_kernel<<<1, 32>>>();                                        // launch 4 (pad: ncu -s 5 hits gemm)
    gemm_kernel<<<dim3(N / BN, M / BM), 256, SMEM_TOTAL>>>(out);     // launch 5 <- profiled
}